// round 1
// baseline (speedup 1.0000x reference)
#include <cuda_runtime.h>
#include <math.h>

#define Bc   8
#define Nc   325
#define Tc   24
#define Dc   64
#define Hc   8
#define Mc   16
#define E2c  128
#define BNc  2600   // Bc*Nc
#define PAD  132    // padded row stride for T x E2 smem tiles (bank spread)

// ---------------- device scratch (sanctioned __device__ globals) ----------------
__device__ float g_tfeat[Bc * Mc];                    // (B,16)
__device__ float g_gcn[(size_t)Bc * Nc * Tc * Dc];    // (B,N,T,D) ~16MB
__device__ float g_weff[(size_t)3 * BNc * E2c * E2c]; // (3,B*N,128,128) ~512MB

__device__ __forceinline__ float lrelu(float x) { return x > 0.f ? x : 0.1f * x; }

// ---------------- Kernel 1: tfeat = tanh(mean_t(tXin[:,0]) @ tproj_w + b) -------
__global__ void k_tfeat(const float* __restrict__ tXin,
                        const float* __restrict__ tpw,
                        const float* __restrict__ tpb) {
    __shared__ float s_mean[Dc];
    int b = blockIdx.x;
    int d = threadIdx.x;  // 64 threads
    const float* p = tXin + (size_t)b * Nc * Tc * Dc;  // n = 0 slice
    float s = 0.f;
    #pragma unroll
    for (int t = 0; t < Tc; t++) s += p[t * Dc + d];
    s_mean[d] = s * (1.0f / Tc);
    __syncthreads();
    if (d < Mc) {
        float acc = tpb[d];
        #pragma unroll
        for (int i = 0; i < Dc; i++) acc += s_mean[i] * tpw[i * Mc + d];
        g_tfeat[b * Mc + d] = tanhf(acc);
    }
}

// ---------------- Kernel 2: support GEMM + GCN (fused) --------------------------
// support[b,n,t,d] = sum_m matrix[b,t,n,m] * hidden[b,m,t,d]
// gcn_out = relu(support @ gcn_w + gcn_b)  -> g_gcn (B,N,T,D)
__global__ __launch_bounds__(256) void k_gcn(const float* __restrict__ matrix,
                                             const float* __restrict__ hidden,
                                             const float* __restrict__ gcn_w,
                                             const float* __restrict__ gcn_b) {
    __shared__ float sA[64][17];
    __shared__ float sB[16][68];
    __shared__ float sS[64][68];
    __shared__ float sW[64][68];
    int tid = threadIdx.x;
    int nt = blockIdx.x, t = blockIdx.y, b = blockIdx.z;
    int n0 = nt * 64;

    for (int idx = tid; idx < 4096; idx += 256) sW[idx >> 6][idx & 63] = gcn_w[idx];

    int ty = tid >> 4, tx = tid & 15;
    int r0 = ty * 4, c0 = tx * 4;
    float acc[4][4] = {};
    const float* Mrow = matrix + ((size_t)(b * Tc + t) * Nc) * Nc;

    for (int kb = 0; kb < 21; kb++) {
        int m0 = kb * 16;
        for (int idx = tid; idx < 1024; idx += 256) {
            int i = idx >> 4, j = idx & 15;
            int n = n0 + i, m = m0 + j;
            sA[i][j] = (n < Nc && m < Nc) ? Mrow[(size_t)n * Nc + m] : 0.f;
        }
        for (int idx = tid; idx < 1024; idx += 256) {
            int j = idx >> 6, d = idx & 63;
            int m = m0 + j;
            sB[j][d] = (m < Nc) ? hidden[((size_t)(b * Nc + m) * Tc + t) * Dc + d] : 0.f;
        }
        __syncthreads();
        #pragma unroll
        for (int j = 0; j < 16; j++) {
            float a0 = sA[r0][j], a1 = sA[r0 + 1][j], a2 = sA[r0 + 2][j], a3 = sA[r0 + 3][j];
            float4 bb = *(const float4*)&sB[j][c0];
            acc[0][0] += a0 * bb.x; acc[0][1] += a0 * bb.y; acc[0][2] += a0 * bb.z; acc[0][3] += a0 * bb.w;
            acc[1][0] += a1 * bb.x; acc[1][1] += a1 * bb.y; acc[1][2] += a1 * bb.z; acc[1][3] += a1 * bb.w;
            acc[2][0] += a2 * bb.x; acc[2][1] += a2 * bb.y; acc[2][2] += a2 * bb.z; acc[2][3] += a2 * bb.w;
            acc[3][0] += a3 * bb.x; acc[3][1] += a3 * bb.y; acc[3][2] += a3 * bb.z; acc[3][3] += a3 * bb.w;
        }
        __syncthreads();
    }
    #pragma unroll
    for (int rr = 0; rr < 4; rr++)
        *(float4*)&sS[r0 + rr][c0] = make_float4(acc[rr][0], acc[rr][1], acc[rr][2], acc[rr][3]);
    __syncthreads();

    float acc2[4][4] = {};
    #pragma unroll
    for (int d = 0; d < 64; d++) {
        float a0 = sS[r0][d], a1 = sS[r0 + 1][d], a2 = sS[r0 + 2][d], a3 = sS[r0 + 3][d];
        float4 w = *(const float4*)&sW[d][c0];
        acc2[0][0] += a0 * w.x; acc2[0][1] += a0 * w.y; acc2[0][2] += a0 * w.z; acc2[0][3] += a0 * w.w;
        acc2[1][0] += a1 * w.x; acc2[1][1] += a1 * w.y; acc2[1][2] += a1 * w.z; acc2[1][3] += a1 * w.w;
        acc2[2][0] += a2 * w.x; acc2[2][1] += a2 * w.y; acc2[2][2] += a2 * w.z; acc2[2][3] += a2 * w.w;
        acc2[3][0] += a3 * w.x; acc2[3][1] += a3 * w.y; acc2[3][2] += a3 * w.z; acc2[3][3] += a3 * w.w;
    }
    float4 gb = *(const float4*)&gcn_b[c0];
    #pragma unroll
    for (int rr = 0; rr < 4; rr++) {
        int n = n0 + r0 + rr;
        if (n < Nc) {
            float4 o;
            o.x = fmaxf(acc2[rr][0] + gb.x, 0.f);
            o.y = fmaxf(acc2[rr][1] + gb.y, 0.f);
            o.z = fmaxf(acc2[rr][2] + gb.z, 0.f);
            o.w = fmaxf(acc2[rr][3] + gb.w, 0.f);
            *(float4*)&g_gcn[((size_t)(b * Nc + n) * Tc + t) * Dc + c0] = o;
        }
    }
}

// ---------------- Kernel 3: Weff[x,bn,:,:] = sum_m emb[bn,m] * W[x][m,:,:] -------
// emb[b,n,m] = node_emb[n,m] * tfeat[b,m]; 8 bn rows share one W tile.
__global__ __launch_bounds__(256) void k_weff(const float* __restrict__ WQ,
                                              const float* __restrict__ WK,
                                              const float* __restrict__ WV,
                                              const float* __restrict__ node_emb) {
    __shared__ float s_w[16][512];
    __shared__ float s_emb[8][16];
    int tid = threadIdx.x;
    int cx = blockIdx.x;   // 32 col-chunks of 512
    int by = blockIdx.y;   // 325 groups of 8 bn rows
    int X  = blockIdx.z;   // 0=Q,1=K,2=V
    const float* W = (X == 0) ? WQ : (X == 1) ? WK : WV;
    int c0 = cx * 512;

    for (int idx4 = tid; idx4 < 2048; idx4 += 256) {
        int m = idx4 >> 7, j4 = idx4 & 127;
        *(float4*)&s_w[m][j4 * 4] = *(const float4*)&W[(size_t)m * 16384 + c0 + j4 * 4];
    }
    if (tid < 128) {
        int row = tid >> 4, m = tid & 15;
        int bn = by * 8 + row;
        int b = bn / Nc, n = bn % Nc;
        s_emb[row][m] = node_emb[n * Mc + m] * g_tfeat[b * Mc + m];
    }
    __syncthreads();

    int j = tid * 2;
    for (int row = 0; row < 8; row++) {
        int bn = by * 8 + row;
        float e[16];
        #pragma unroll
        for (int m = 0; m < 16; m++) e[m] = s_emb[row][m];
        float a0 = 0.f, a1 = 0.f;
        #pragma unroll
        for (int m = 0; m < 16; m++) {
            float2 w2 = *(const float2*)&s_w[m][j];
            a0 += e[m] * w2.x;
            a1 += e[m] * w2.y;
        }
        *(float2*)&g_weff[((size_t)X * BNc + bn) * 16384 + c0 + j] = make_float2(a0, a1);
    }
}

// ---------------- Kernel 4: fused per-(b,n) attention path ----------------------
// qkv -> q/k/v proj (lrelu) -> causal softmax attention -> AV -> out proj (lrelu)
// -> gate with gcn_out -> + hidden residual -> out
__global__ __launch_bounds__(256, 2) void k_attn(const float* __restrict__ hidden,
                                                 const float* __restrict__ tXin,
                                                 const float* __restrict__ out_w,
                                                 const float* __restrict__ out_b,
                                                 const float* __restrict__ gate_w,
                                                 const float* __restrict__ gate_b,
                                                 float* __restrict__ out) {
    extern __shared__ float sm[];
    float* s_qkv   = sm;                   // 24*132
    float* s_q     = s_qkv + 24 * PAD;     // 24*132
    float* s_k     = s_q + 24 * PAD;       // 24*132
    float* s_v     = s_k + 24 * PAD;       // 24*132
    float* s_val   = s_v + 24 * PAD;       // 24*132
    float* s_w     = s_val + 24 * PAD;     // 16*128
    float* s_sc    = s_w + 2048;           // 8*577
    float* s_value = s_sc + 8 * 577;       // 24*64
    float* s_gcn   = s_value + 24 * 64;    // 24*64

    int tid = threadIdx.x;
    int bn = blockIdx.x;
    size_t base = (size_t)bn * (Tc * Dc);  // bn == b*N + n

    for (int idx = tid; idx < 3072; idx += 256) {
        int t = idx >> 7, i = idx & 127;
        float vv = (i < 64) ? hidden[base + t * 64 + i] : tXin[base + t * 64 + (i - 64)];
        s_qkv[t * PAD + i] = vv;
    }
    for (int idx = tid; idx < 1536; idx += 256) s_gcn[idx] = g_gcn[base + idx];
    __syncthreads();

    int kg = tid & 31, tg = tid >> 5;  // 32 k-groups x 8 t-groups
    int k0 = kg * 4;

    // ---- QKV projection: (24x128) @ Weff(128x128), lrelu ----
    for (int X = 0; X < 3; X++) {
        const float* wp = g_weff + ((size_t)X * BNc + bn) * 16384;
        float acc[3][4] = {};
        for (int it = 0; it < 8; it++) {
            const float4* src = (const float4*)(wp + it * 2048);
            for (int v4 = tid; v4 < 512; v4 += 256) ((float4*)s_w)[v4] = src[v4];
            __syncthreads();
            #pragma unroll
            for (int i = 0; i < 16; i++) {
                float4 w4 = *(const float4*)&s_w[i * 128 + k0];
                int ig = it * 16 + i;
                #pragma unroll
                for (int j = 0; j < 3; j++) {
                    float a = s_qkv[(tg * 3 + j) * PAD + ig];
                    acc[j][0] += a * w4.x; acc[j][1] += a * w4.y;
                    acc[j][2] += a * w4.z; acc[j][3] += a * w4.w;
                }
            }
            __syncthreads();
        }
        float* dst = (X == 0) ? s_q : (X == 1) ? s_k : s_v;
        #pragma unroll
        for (int j = 0; j < 3; j++) {
            int t = tg * 3 + j;
            float4 o;
            o.x = lrelu(acc[j][0]); o.y = lrelu(acc[j][1]);
            o.z = lrelu(acc[j][2]); o.w = lrelu(acc[j][3]);
            *(float4*)&dst[t * PAD + k0] = o;
        }
    }
    __syncthreads();

    // ---- scores (causal) : scale * q.k per head ----
    for (int idx = tid; idx < 4608; idx += 256) {
        int h = idx / 576; int r = idx - h * 576; int t = r / 24; int s = r - t * 24;
        if (s <= t) {
            const float* qp = &s_q[t * PAD + h * 16];
            const float* kp = &s_k[s * PAD + h * 16];
            float d = 0.f;
            #pragma unroll
            for (int e = 0; e < 16; e++) d += qp[e] * kp[e];
            s_sc[h * 577 + t * 24 + s] = 0.25f * d;  // 1/sqrt(16)
        }
    }
    __syncthreads();

    // ---- softmax per (h,t) row ----
    if (tid < 192) {
        int h = tid / 24, t = tid % 24;
        float* row = &s_sc[h * 577 + t * 24];
        float mx = -1e30f;
        for (int s = 0; s <= t; s++) mx = fmaxf(mx, row[s]);
        float sum = 0.f;
        for (int s = 0; s <= t; s++) { float e = expf(row[s] - mx); row[s] = e; sum += e; }
        float inv = 1.f / sum;
        for (int s = 0; s < Tc; s++) row[s] = (s <= t) ? row[s] * inv : 0.f;
    }
    __syncthreads();

    // ---- val = attn @ v ----
    {
        int h = k0 >> 4;
        float acc[3][4] = {};
        #pragma unroll
        for (int s = 0; s < Tc; s++) {
            float4 v4 = *(const float4*)&s_v[s * PAD + k0];
            #pragma unroll
            for (int j = 0; j < 3; j++) {
                float a = s_sc[h * 577 + (tg * 3 + j) * 24 + s];
                acc[j][0] += a * v4.x; acc[j][1] += a * v4.y;
                acc[j][2] += a * v4.z; acc[j][3] += a * v4.w;
            }
        }
        #pragma unroll
        for (int j = 0; j < 3; j++) {
            int t = tg * 3 + j;
            *(float4*)&s_val[t * PAD + k0] =
                make_float4(acc[j][0], acc[j][1], acc[j][2], acc[j][3]);
        }
    }
    __syncthreads();

    // ---- value = lrelu(val @ out_w + out_b) ----
    int e0 = (tid & 15) * 4;
    int tg2 = tid >> 4;               // 0..15
    int t0 = tg2, t1 = tg2 + 16;
    int t1c = (t1 < Tc) ? t1 : 0;
    {
        float a0[4] = {}, a1[4] = {};
        #pragma unroll 4
        for (int i = 0; i < 128; i++) {
            float4 w4 = *(const float4*)&out_w[i * 64 + e0];
            float x0 = s_val[t0 * PAD + i];
            float x1 = s_val[t1c * PAD + i];
            a0[0] += x0 * w4.x; a0[1] += x0 * w4.y; a0[2] += x0 * w4.z; a0[3] += x0 * w4.w;
            a1[0] += x1 * w4.x; a1[1] += x1 * w4.y; a1[2] += x1 * w4.z; a1[3] += x1 * w4.w;
        }
        float4 ob = *(const float4*)&out_b[e0];
        float4 v0;
        v0.x = lrelu(a0[0] + ob.x); v0.y = lrelu(a0[1] + ob.y);
        v0.z = lrelu(a0[2] + ob.z); v0.w = lrelu(a0[3] + ob.w);
        *(float4*)&s_value[t0 * 64 + e0] = v0;
        if (t1 < Tc) {
            float4 v1;
            v1.x = lrelu(a1[0] + ob.x); v1.y = lrelu(a1[1] + ob.y);
            v1.z = lrelu(a1[2] + ob.z); v1.w = lrelu(a1[3] + ob.w);
            *(float4*)&s_value[t1 * 64 + e0] = v1;
        }
    }
    __syncthreads();

    // ---- gate + blend + residual ----
    {
        float g0[4] = {}, g1[4] = {};
        #pragma unroll 4
        for (int i = 0; i < 64; i++) {
            float4 w4 = *(const float4*)&gate_w[i * 64 + e0];
            float x0 = s_gcn[t0 * 64 + i];
            float x1 = s_gcn[t1c * 64 + i];
            g0[0] += x0 * w4.x; g0[1] += x0 * w4.y; g0[2] += x0 * w4.z; g0[3] += x0 * w4.w;
            g1[0] += x1 * w4.x; g1[1] += x1 * w4.y; g1[2] += x1 * w4.z; g1[3] += x1 * w4.w;
        }
        #pragma unroll 4
        for (int i = 0; i < 64; i++) {
            float4 w4 = *(const float4*)&gate_w[(64 + i) * 64 + e0];
            float x0 = s_value[t0 * 64 + i];
            float x1 = s_value[t1c * 64 + i];
            g0[0] += x0 * w4.x; g0[1] += x0 * w4.y; g0[2] += x0 * w4.z; g0[3] += x0 * w4.w;
            g1[0] += x1 * w4.x; g1[1] += x1 * w4.y; g1[2] += x1 * w4.z; g1[3] += x1 * w4.w;
        }
        float4 gb = *(const float4*)&gate_b[e0];
        {
            float4 hd = *(const float4*)&hidden[base + t0 * 64 + e0];
            float zx = 1.f / (1.f + expf(-(g0[0] + gb.x)));
            float zy = 1.f / (1.f + expf(-(g0[1] + gb.y)));
            float zz = 1.f / (1.f + expf(-(g0[2] + gb.z)));
            float zw = 1.f / (1.f + expf(-(g0[3] + gb.w)));
            const float* gc = &s_gcn[t0 * 64 + e0];
            const float* vv = &s_value[t0 * 64 + e0];
            float4 o;
            o.x = zx * gc[0] + (1.f - zx) * vv[0] + hd.x;
            o.y = zy * gc[1] + (1.f - zy) * vv[1] + hd.y;
            o.z = zz * gc[2] + (1.f - zz) * vv[2] + hd.z;
            o.w = zw * gc[3] + (1.f - zw) * vv[3] + hd.w;
            *(float4*)&out[base + t0 * 64 + e0] = o;
        }
        if (t1 < Tc) {
            float4 hd = *(const float4*)&hidden[base + t1 * 64 + e0];
            float zx = 1.f / (1.f + expf(-(g1[0] + gb.x)));
            float zy = 1.f / (1.f + expf(-(g1[1] + gb.y)));
            float zz = 1.f / (1.f + expf(-(g1[2] + gb.z)));
            float zw = 1.f / (1.f + expf(-(g1[3] + gb.w)));
            const float* gc = &s_gcn[t1 * 64 + e0];
            const float* vv = &s_value[t1 * 64 + e0];
            float4 o;
            o.x = zx * gc[0] + (1.f - zx) * vv[0] + hd.x;
            o.y = zy * gc[1] + (1.f - zy) * vv[1] + hd.y;
            o.z = zz * gc[2] + (1.f - zz) * vv[2] + hd.z;
            o.w = zw * gc[3] + (1.f - zw) * vv[3] + hd.w;
            *(float4*)&out[base + t1 * 64 + e0] = o;
        }
    }
}

// ---------------- launch ----------------
#define ATTN_SMEM_FLOATS (5 * 24 * PAD + 2048 + 8 * 577 + 2 * 24 * 64)
#define ATTN_SMEM_BYTES  (ATTN_SMEM_FLOATS * 4)

extern "C" void kernel_launch(void* const* d_in, const int* in_sizes, int n_in,
                              void* d_out, int out_size) {
    const float* hidden   = (const float*)d_in[0];
    const float* tXin     = (const float*)d_in[1];
    const float* matrix   = (const float*)d_in[2];
    const float* gcn_w    = (const float*)d_in[3];
    const float* gcn_b    = (const float*)d_in[4];
    const float* node_emb = (const float*)d_in[5];
    const float* tproj_w  = (const float*)d_in[6];
    const float* tproj_b  = (const float*)d_in[7];
    const float* WK       = (const float*)d_in[8];
    const float* WQ       = (const float*)d_in[9];
    const float* WV       = (const float*)d_in[10];
    const float* out_w    = (const float*)d_in[11];
    const float* out_b    = (const float*)d_in[12];
    const float* gate_w   = (const float*)d_in[13];
    const float* gate_b   = (const float*)d_in[14];
    float* out = (float*)d_out;

    cudaFuncSetAttribute(k_attn, cudaFuncAttributeMaxDynamicSharedMemorySize, ATTN_SMEM_BYTES);

    k_tfeat<<<Bc, 64>>>(tXin, tproj_w, tproj_b);
    k_gcn<<<dim3(6, Tc, Bc), 256>>>(matrix, hidden, gcn_w, gcn_b);
    k_weff<<<dim3(32, 325, 3), 256>>>(WQ, WK, WV, node_emb);
    k_attn<<<BNc, 256, ATTN_SMEM_BYTES>>>(hidden, tXin, out_w, out_b, gate_w, gate_b, out);
}

// round 2
// speedup vs baseline: 1.5235x; 1.5235x over previous
#include <cuda_runtime.h>
#include <math.h>

#define Bc   8
#define Nc   325
#define Tc   24
#define Dc   64
#define Hc   8
#define Mc   16
#define E2c  128
#define BNc  2600   // Bc*Nc
#define PAD  132    // padded row stride for T x E2 smem tiles

// ---------------- device scratch ----------------
__device__ float g_tfeat[Bc * Mc];                    // (B,16)
__device__ float g_gcn[(size_t)Bc * Nc * Tc * Dc];    // (B,N,T,D) ~16MB
__device__ float g_weff[(size_t)3 * BNc * E2c * E2c]; // (3,B*N,128,128) ~512MB

__device__ __forceinline__ float lrelu(float x) { return x > 0.f ? x : 0.1f * x; }

#define CP_ASYNC16(sdst, gsrc) \
    asm volatile("cp.async.cg.shared.global [%0], [%1], 16;" :: "r"(sdst), "l"(gsrc) : "memory")
#define CP_COMMIT() asm volatile("cp.async.commit_group;" ::: "memory")
#define CP_WAIT1()  asm volatile("cp.async.wait_group 1;" ::: "memory")
#define CP_WAIT0()  asm volatile("cp.async.wait_group 0;" ::: "memory")

// ---------------- Kernel 1: tfeat ----------------
__global__ void k_tfeat(const float* __restrict__ tXin,
                        const float* __restrict__ tpw,
                        const float* __restrict__ tpb) {
    __shared__ float s_mean[Dc];
    int b = blockIdx.x;
    int d = threadIdx.x;  // 64 threads
    const float* p = tXin + (size_t)b * Nc * Tc * Dc;  // n = 0 slice
    float s = 0.f;
    #pragma unroll
    for (int t = 0; t < Tc; t++) s += p[t * Dc + d];
    s_mean[d] = s * (1.0f / Tc);
    __syncthreads();
    if (d < Mc) {
        float acc = tpb[d];
        #pragma unroll
        for (int i = 0; i < Dc; i++) acc += s_mean[i] * tpw[i * Mc + d];
        g_tfeat[b * Mc + d] = tanhf(acc);
    }
}

// ---------------- Kernel 2: support GEMM + GCN (fused) --------------------------
__global__ __launch_bounds__(256) void k_gcn(const float* __restrict__ matrix,
                                             const float* __restrict__ hidden,
                                             const float* __restrict__ gcn_w,
                                             const float* __restrict__ gcn_b) {
    __shared__ float sA[64][17];
    __shared__ float sB[16][68];
    __shared__ float sS[64][68];
    __shared__ float sW[64][68];
    int tid = threadIdx.x;
    int nt = blockIdx.x, t = blockIdx.y, b = blockIdx.z;
    int n0 = nt * 64;

    for (int idx = tid; idx < 4096; idx += 256) sW[idx >> 6][idx & 63] = gcn_w[idx];

    int ty = tid >> 4, tx = tid & 15;
    int r0 = ty * 4, c0 = tx * 4;
    float acc[4][4] = {};
    const float* Mrow = matrix + ((size_t)(b * Tc + t) * Nc) * Nc;

    for (int kb = 0; kb < 21; kb++) {
        int m0 = kb * 16;
        for (int idx = tid; idx < 1024; idx += 256) {
            int i = idx >> 4, j = idx & 15;
            int n = n0 + i, m = m0 + j;
            sA[i][j] = (n < Nc && m < Nc) ? Mrow[(size_t)n * Nc + m] : 0.f;
        }
        for (int idx = tid; idx < 1024; idx += 256) {
            int j = idx >> 6, d = idx & 63;
            int m = m0 + j;
            sB[j][d] = (m < Nc) ? hidden[((size_t)(b * Nc + m) * Tc + t) * Dc + d] : 0.f;
        }
        __syncthreads();
        #pragma unroll
        for (int j = 0; j < 16; j++) {
            float a0 = sA[r0][j], a1 = sA[r0 + 1][j], a2 = sA[r0 + 2][j], a3 = sA[r0 + 3][j];
            float4 bb = *(const float4*)&sB[j][c0];
            acc[0][0] += a0 * bb.x; acc[0][1] += a0 * bb.y; acc[0][2] += a0 * bb.z; acc[0][3] += a0 * bb.w;
            acc[1][0] += a1 * bb.x; acc[1][1] += a1 * bb.y; acc[1][2] += a1 * bb.z; acc[1][3] += a1 * bb.w;
            acc[2][0] += a2 * bb.x; acc[2][1] += a2 * bb.y; acc[2][2] += a2 * bb.z; acc[2][3] += a2 * bb.w;
            acc[3][0] += a3 * bb.x; acc[3][1] += a3 * bb.y; acc[3][2] += a3 * bb.z; acc[3][3] += a3 * bb.w;
        }
        __syncthreads();
    }
    #pragma unroll
    for (int rr = 0; rr < 4; rr++)
        *(float4*)&sS[r0 + rr][c0] = make_float4(acc[rr][0], acc[rr][1], acc[rr][2], acc[rr][3]);
    __syncthreads();

    float acc2[4][4] = {};
    #pragma unroll
    for (int d = 0; d < 64; d++) {
        float a0 = sS[r0][d], a1 = sS[r0 + 1][d], a2 = sS[r0 + 2][d], a3 = sS[r0 + 3][d];
        float4 w = *(const float4*)&sW[d][c0];
        acc2[0][0] += a0 * w.x; acc2[0][1] += a0 * w.y; acc2[0][2] += a0 * w.z; acc2[0][3] += a0 * w.w;
        acc2[1][0] += a1 * w.x; acc2[1][1] += a1 * w.y; acc2[1][2] += a1 * w.z; acc2[1][3] += a1 * w.w;
        acc2[2][0] += a2 * w.x; acc2[2][1] += a2 * w.y; acc2[2][2] += a2 * w.z; acc2[2][3] += a2 * w.w;
        acc2[3][0] += a3 * w.x; acc2[3][1] += a3 * w.y; acc2[3][2] += a3 * w.z; acc2[3][3] += a3 * w.w;
    }
    float4 gb = *(const float4*)&gcn_b[c0];
    #pragma unroll
    for (int rr = 0; rr < 4; rr++) {
        int n = n0 + r0 + rr;
        if (n < Nc) {
            float4 o;
            o.x = fmaxf(acc2[rr][0] + gb.x, 0.f);
            o.y = fmaxf(acc2[rr][1] + gb.y, 0.f);
            o.z = fmaxf(acc2[rr][2] + gb.z, 0.f);
            o.w = fmaxf(acc2[rr][3] + gb.w, 0.f);
            *(float4*)&g_gcn[((size_t)(b * Nc + n) * Tc + t) * Dc + c0] = o;
        }
    }
}

// ---------------- Kernel 3: Weff build, W in registers, 32 bn rows/block --------
__global__ __launch_bounds__(256) void k_weff(const float* __restrict__ WQ,
                                              const float* __restrict__ WK,
                                              const float* __restrict__ WV,
                                              const float* __restrict__ node_emb) {
    __shared__ float s_emb[32][16];
    int tid = threadIdx.x;
    int cx = blockIdx.x;   // 16 chunks of 1024 cols
    int by = blockIdx.y;   // 82 groups of 32 bn rows
    int X  = blockIdx.z;   // 0=Q,1=K,2=V
    const float* W = (X == 0) ? WQ : (X == 1) ? WK : WV;
    int c0 = cx * 1024 + tid * 4;

    float4 w[16];
    #pragma unroll
    for (int m = 0; m < 16; m++) w[m] = *(const float4*)&W[(size_t)m * 16384 + c0];

    for (int idx = tid; idx < 512; idx += 256) {
        int row = idx >> 4, m = idx & 15;
        int bn = by * 32 + row;
        if (bn < BNc) {
            int b = bn / Nc, n = bn - b * Nc;
            s_emb[row][m] = node_emb[n * Mc + m] * g_tfeat[b * Mc + m];
        }
    }
    __syncthreads();

    #pragma unroll 4
    for (int row = 0; row < 32; row++) {
        int bn = by * 32 + row;
        if (bn >= BNc) break;
        float4 acc = make_float4(0.f, 0.f, 0.f, 0.f);
        #pragma unroll
        for (int m = 0; m < 16; m++) {
            float e = s_emb[row][m];
            acc.x += e * w[m].x; acc.y += e * w[m].y;
            acc.z += e * w[m].z; acc.w += e * w[m].w;
        }
        *(float4*)&g_weff[((size_t)X * BNc + bn) * 16384 + c0] = acc;
    }
}

// ---------------- Kernel 4: fused per-(b,n) attention path ----------------------
// smem layout (floats):
//   [0, 3168)        s_qkv          (proj phase)   | s_sc (4800) + s_value(1536) + s_gcn(1536) (post phase)
//   [3168, 9312)     s_w double buf (proj phase)   |   (overlay continues)
//   [9312, 12480)    s_q   | s_val (post-AV overlay)
//   [12480, 15648)   s_k
//   [15648, 18816)   s_v
#define ATTN_SMEM_FLOATS 18816
#define ATTN_SMEM_BYTES  (ATTN_SMEM_FLOATS * 4)

__global__ __launch_bounds__(256, 3) void k_attn(const float* __restrict__ hidden,
                                                 const float* __restrict__ tXin,
                                                 const float* __restrict__ out_w,
                                                 const float* __restrict__ out_b,
                                                 const float* __restrict__ gate_w,
                                                 const float* __restrict__ gate_b,
                                                 float* __restrict__ out) {
    extern __shared__ float sm[];
    float* s_qkv   = sm;               // 24*132
    float* s_w     = sm + 3168;        // 2 * 3 * 1024
    float* s_sc    = sm;               // 8*24*25 (overlay)
    float* s_value = sm + 4800;        // 24*64
    float* s_gcn   = sm + 6336;        // 24*64
    float* s_q     = sm + 9312;        // 24*132
    float* s_k     = sm + 12480;
    float* s_v     = sm + 15648;
    float* s_val   = s_q;              // overlay after scores

    int tid = threadIdx.x;
    int bn  = blockIdx.x;
    size_t base = (size_t)bn * (Tc * Dc);

    // ---- stage qkv ----
    for (int idx = tid; idx < 3072; idx += 256) {
        int t = idx >> 7, i = idx & 127;
        float vv = (i < 64) ? hidden[base + t * 64 + i] : tXin[base + t * 64 + (i - 64)];
        s_qkv[t * PAD + i] = vv;
    }

    const float* wq = g_weff + (size_t)bn * 16384;
    const float* wk = g_weff + ((size_t)BNc + bn) * 16384;
    const float* wv = g_weff + ((size_t)2 * BNc + bn) * 16384;

    unsigned s_w_base = (unsigned)__cvta_generic_to_shared(s_w);
    // prefetch chunk 0 into buf 0 (1024 floats per X, 1 float4/thread/X)
    {
        unsigned d = s_w_base + tid * 16;
        CP_ASYNC16(d,            wq + tid * 4);
        CP_ASYNC16(d + 4096,     wk + tid * 4);
        CP_ASYNC16(d + 8192,     wv + tid * 4);
        CP_COMMIT();
    }

    int kg = tid & 31, tg = tid >> 5;
    int k0 = kg * 4;
    float acc[3][12] = {};

    int buf = 0;
    for (int it = 0; it < 16; it++) {
        if (it < 15) {
            unsigned d = s_w_base + (buf ^ 1) * 12288 + tid * 16;
            int off = (it + 1) * 1024 + tid * 4;
            CP_ASYNC16(d,        wq + off);
            CP_ASYNC16(d + 4096, wk + off);
            CP_ASYNC16(d + 8192, wv + off);
            CP_COMMIT();
            CP_WAIT1();
        } else {
            CP_WAIT0();
        }
        __syncthreads();
        const float* wb = s_w + buf * 3072;
        #pragma unroll
        for (int i = 0; i < 8; i++) {
            int ig = it * 8 + i;
            float a0 = s_qkv[(tg * 3 + 0) * PAD + ig];
            float a1 = s_qkv[(tg * 3 + 1) * PAD + ig];
            float a2 = s_qkv[(tg * 3 + 2) * PAD + ig];
            #pragma unroll
            for (int X = 0; X < 3; X++) {
                float4 w4 = *(const float4*)&wb[X * 1024 + i * 128 + k0];
                float* A = acc[X];
                A[0] += a0 * w4.x; A[1]  += a0 * w4.y; A[2]  += a0 * w4.z; A[3]  += a0 * w4.w;
                A[4] += a1 * w4.x; A[5]  += a1 * w4.y; A[6]  += a1 * w4.z; A[7]  += a1 * w4.w;
                A[8] += a2 * w4.x; A[9]  += a2 * w4.y; A[10] += a2 * w4.z; A[11] += a2 * w4.w;
            }
        }
        __syncthreads();
        buf ^= 1;
    }

    // ---- store q,k,v with lrelu ----
    #pragma unroll
    for (int X = 0; X < 3; X++) {
        float* dst = (X == 0) ? s_q : (X == 1) ? s_k : s_v;
        #pragma unroll
        for (int j = 0; j < 3; j++) {
            int t = tg * 3 + j;
            float4 o;
            o.x = lrelu(acc[X][j * 4 + 0]); o.y = lrelu(acc[X][j * 4 + 1]);
            o.z = lrelu(acc[X][j * 4 + 2]); o.w = lrelu(acc[X][j * 4 + 3]);
            *(float4*)&dst[t * PAD + k0] = o;
        }
    }
    __syncthreads();

    // ---- load gcn (overlay region) + scores (causal) ----
    for (int idx = tid; idx < 1536; idx += 256) s_gcn[idx] = g_gcn[base + idx];
    for (int idx = tid; idx < 4608; idx += 256) {
        int h = idx / 576; int r = idx - h * 576; int t = r / 24; int s = r - t * 24;
        if (s <= t) {
            const float* qp = &s_q[t * PAD + h * 16];
            const float* kp = &s_k[s * PAD + h * 16];
            float d = 0.f;
            #pragma unroll
            for (int e = 0; e < 16; e++) d += qp[e] * kp[e];
            s_sc[h * 600 + t * 25 + s] = 0.25f * d;  // 1/sqrt(16)
        }
    }
    __syncthreads();

    // ---- softmax per (h,t) row ----
    if (tid < 192) {
        int h = tid / 24, t = tid % 24;
        float* row = &s_sc[h * 600 + t * 25];
        float mx = -1e30f;
        for (int s = 0; s <= t; s++) mx = fmaxf(mx, row[s]);
        float sum = 0.f;
        for (int s = 0; s <= t; s++) { float e = expf(row[s] - mx); row[s] = e; sum += e; }
        float inv = 1.f / sum;
        for (int s = 0; s < Tc; s++) row[s] = (s <= t) ? row[s] * inv : 0.f;
    }
    __syncthreads();

    // ---- val = attn @ v  (writes overlay s_q) ----
    {
        int h = k0 >> 4;
        float a2[12] = {};
        #pragma unroll
        for (int s = 0; s < Tc; s++) {
            float4 v4 = *(const float4*)&s_v[s * PAD + k0];
            #pragma unroll
            for (int j = 0; j < 3; j++) {
                float a = s_sc[h * 600 + (tg * 3 + j) * 25 + s];
                a2[j * 4 + 0] += a * v4.x; a2[j * 4 + 1] += a * v4.y;
                a2[j * 4 + 2] += a * v4.z; a2[j * 4 + 3] += a * v4.w;
            }
        }
        __syncthreads();  // ensure all scores reads done before overwriting s_q
        #pragma unroll
        for (int j = 0; j < 3; j++) {
            int t = tg * 3 + j;
            *(float4*)&s_val[t * PAD + k0] =
                make_float4(a2[j * 4 + 0], a2[j * 4 + 1], a2[j * 4 + 2], a2[j * 4 + 3]);
        }
    }
    __syncthreads();

    // ---- value = lrelu(val @ out_w + out_b) ----
    int e0 = (tid & 15) * 4;
    int tg2 = tid >> 4;               // 0..15
    int t0 = tg2, t1 = tg2 + 16;
    int t1c = (t1 < Tc) ? t1 : 0;
    {
        float a0[4] = {}, a1[4] = {};
        #pragma unroll 4
        for (int i = 0; i < 128; i++) {
            float4 w4 = *(const float4*)&out_w[i * 64 + e0];
            float x0 = s_val[t0 * PAD + i];
            float x1 = s_val[t1c * PAD + i];
            a0[0] += x0 * w4.x; a0[1] += x0 * w4.y; a0[2] += x0 * w4.z; a0[3] += x0 * w4.w;
            a1[0] += x1 * w4.x; a1[1] += x1 * w4.y; a1[2] += x1 * w4.z; a1[3] += x1 * w4.w;
        }
        float4 ob = *(const float4*)&out_b[e0];
        float4 v0;
        v0.x = lrelu(a0[0] + ob.x); v0.y = lrelu(a0[1] + ob.y);
        v0.z = lrelu(a0[2] + ob.z); v0.w = lrelu(a0[3] + ob.w);
        *(float4*)&s_value[t0 * 64 + e0] = v0;
        if (t1 < Tc) {
            float4 v1;
            v1.x = lrelu(a1[0] + ob.x); v1.y = lrelu(a1[1] + ob.y);
            v1.z = lrelu(a1[2] + ob.z); v1.w = lrelu(a1[3] + ob.w);
            *(float4*)&s_value[t1 * 64 + e0] = v1;
        }
    }
    __syncthreads();

    // ---- gate + blend + residual ----
    {
        float g0[4] = {}, g1[4] = {};
        #pragma unroll 4
        for (int i = 0; i < 64; i++) {
            float4 w4 = *(const float4*)&gate_w[i * 64 + e0];
            float x0 = s_gcn[t0 * 64 + i];
            float x1 = s_gcn[t1c * 64 + i];
            g0[0] += x0 * w4.x; g0[1] += x0 * w4.y; g0[2] += x0 * w4.z; g0[3] += x0 * w4.w;
            g1[0] += x1 * w4.x; g1[1] += x1 * w4.y; g1[2] += x1 * w4.z; g1[3] += x1 * w4.w;
        }
        #pragma unroll 4
        for (int i = 0; i < 64; i++) {
            float4 w4 = *(const float4*)&gate_w[(64 + i) * 64 + e0];
            float x0 = s_value[t0 * 64 + i];
            float x1 = s_value[t1c * 64 + i];
            g0[0] += x0 * w4.x; g0[1] += x0 * w4.y; g0[2] += x0 * w4.z; g0[3] += x0 * w4.w;
            g1[0] += x1 * w4.x; g1[1] += x1 * w4.y; g1[2] += x1 * w4.z; g1[3] += x1 * w4.w;
        }
        float4 gb = *(const float4*)&gate_b[e0];
        {
            float4 hd = *(const float4*)&hidden[base + t0 * 64 + e0];
            float zx = 1.f / (1.f + expf(-(g0[0] + gb.x)));
            float zy = 1.f / (1.f + expf(-(g0[1] + gb.y)));
            float zz = 1.f / (1.f + expf(-(g0[2] + gb.z)));
            float zw = 1.f / (1.f + expf(-(g0[3] + gb.w)));
            const float* gc = &s_gcn[t0 * 64 + e0];
            const float* vv = &s_value[t0 * 64 + e0];
            float4 o;
            o.x = zx * gc[0] + (1.f - zx) * vv[0] + hd.x;
            o.y = zy * gc[1] + (1.f - zy) * vv[1] + hd.y;
            o.z = zz * gc[2] + (1.f - zz) * vv[2] + hd.z;
            o.w = zw * gc[3] + (1.f - zw) * vv[3] + hd.w;
            *(float4*)&out[base + t0 * 64 + e0] = o;
        }
        if (t1 < Tc) {
            float4 hd = *(const float4*)&hidden[base + t1 * 64 + e0];
            float zx = 1.f / (1.f + expf(-(g1[0] + gb.x)));
            float zy = 1.f / (1.f + expf(-(g1[1] + gb.y)));
            float zz = 1.f / (1.f + expf(-(g1[2] + gb.z)));
            float zw = 1.f / (1.f + expf(-(g1[3] + gb.w)));
            const float* gc = &s_gcn[t1 * 64 + e0];
            const float* vv = &s_value[t1 * 64 + e0];
            float4 o;
            o.x = zx * gc[0] + (1.f - zx) * vv[0] + hd.x;
            o.y = zy * gc[1] + (1.f - zy) * vv[1] + hd.y;
            o.z = zz * gc[2] + (1.f - zz) * vv[2] + hd.z;
            o.w = zw * gc[3] + (1.f - zw) * vv[3] + hd.w;
            *(float4*)&out[base + t1 * 64 + e0] = o;
        }
    }
}

// ---------------- launch ----------------
extern "C" void kernel_launch(void* const* d_in, const int* in_sizes, int n_in,
                              void* d_out, int out_size) {
    const float* hidden   = (const float*)d_in[0];
    const float* tXin     = (const float*)d_in[1];
    const float* matrix   = (const float*)d_in[2];
    const float* gcn_w    = (const float*)d_in[3];
    const float* gcn_b    = (const float*)d_in[4];
    const float* node_emb = (const float*)d_in[5];
    const float* tproj_w  = (const float*)d_in[6];
    const float* tproj_b  = (const float*)d_in[7];
    const float* WK       = (const float*)d_in[8];
    const float* WQ       = (const float*)d_in[9];
    const float* WV       = (const float*)d_in[10];
    const float* out_w    = (const float*)d_in[11];
    const float* out_b    = (const float*)d_in[12];
    const float* gate_w   = (const float*)d_in[13];
    const float* gate_b   = (const float*)d_in[14];
    float* out = (float*)d_out;

    cudaFuncSetAttribute(k_attn, cudaFuncAttributeMaxDynamicSharedMemorySize, ATTN_SMEM_BYTES);

    k_tfeat<<<Bc, 64>>>(tXin, tproj_w, tproj_b);
    k_gcn<<<dim3(6, Tc, Bc), 256>>>(matrix, hidden, gcn_w, gcn_b);
    k_weff<<<dim3(16, 82, 3), 256>>>(WQ, WK, WV, node_emb);
    k_attn<<<BNc, 256, ATTN_SMEM_BYTES>>>(hidden, tXin, out_w, out_b, gate_w, gate_b, out);
}

// round 4
// speedup vs baseline: 1.6178x; 1.0619x over previous
#include <cuda_runtime.h>
#include <cuda_fp16.h>
#include <math.h>

#define Bc   8
#define Nc   325
#define Tc   24
#define Dc   64
#define Hc   8
#define Mc   16
#define E2c  128
#define BNc  2600   // Bc*Nc
#define PAD  132    // padded row stride for T x E2 smem tiles

// ---------------- device scratch ----------------
__device__ float g_tfeat[Bc * Mc];                            // (B,16)
__device__ float g_gcn[(size_t)Bc * Nc * Tc * Dc];            // (B,N,T,D) ~16MB
__device__ __align__(16) __half g_weff[(size_t)3 * BNc * E2c * E2c]; // fp16 ~256MB

__device__ __forceinline__ float lrelu(float x) { return x > 0.f ? x : 0.1f * x; }

#define CP_ASYNC16(sdst, gsrc) \
    asm volatile("cp.async.cg.shared.global [%0], [%1], 16;" :: "r"(sdst), "l"(gsrc) : "memory")
#define CP_COMMIT() asm volatile("cp.async.commit_group;" ::: "memory")
#define CP_WAIT1()  asm volatile("cp.async.wait_group 1;" ::: "memory")
#define CP_WAIT0()  asm volatile("cp.async.wait_group 0;" ::: "memory")

// ---------------- Kernel 1: tfeat ----------------
__global__ void k_tfeat(const float* __restrict__ tXin,
                        const float* __restrict__ tpw,
                        const float* __restrict__ tpb) {
    __shared__ float s_mean[Dc];
    int b = blockIdx.x;
    int d = threadIdx.x;  // 64 threads
    const float* p = tXin + (size_t)b * Nc * Tc * Dc;  // n = 0 slice
    float s = 0.f;
    #pragma unroll
    for (int t = 0; t < Tc; t++) s += p[t * Dc + d];
    s_mean[d] = s * (1.0f / Tc);
    __syncthreads();
    if (d < Mc) {
        float acc = tpb[d];
        #pragma unroll
        for (int i = 0; i < Dc; i++) acc += s_mean[i] * tpw[i * Mc + d];
        g_tfeat[b * Mc + d] = tanhf(acc);
    }
}

// ---------------- Kernel 2: support GEMM + GCN (fused) --------------------------
__global__ __launch_bounds__(256) void k_gcn(const float* __restrict__ matrix,
                                             const float* __restrict__ hidden,
                                             const float* __restrict__ gcn_w,
                                             const float* __restrict__ gcn_b) {
    __shared__ float sA[64][17];
    __shared__ float sB[16][68];
    __shared__ float sS[64][68];
    __shared__ float sW[64][68];
    int tid = threadIdx.x;
    int nt = blockIdx.x, t = blockIdx.y, b = blockIdx.z;
    int n0 = nt * 64;

    for (int idx = tid; idx < 4096; idx += 256) sW[idx >> 6][idx & 63] = gcn_w[idx];

    int ty = tid >> 4, tx = tid & 15;
    int r0 = ty * 4, c0 = tx * 4;
    float acc[4][4] = {};
    const float* Mrow = matrix + ((size_t)(b * Tc + t) * Nc) * Nc;

    for (int kb = 0; kb < 21; kb++) {
        int m0 = kb * 16;
        for (int idx = tid; idx < 1024; idx += 256) {
            int i = idx >> 4, j = idx & 15;
            int n = n0 + i, m = m0 + j;
            sA[i][j] = (n < Nc && m < Nc) ? Mrow[(size_t)n * Nc + m] : 0.f;
        }
        for (int idx = tid; idx < 1024; idx += 256) {
            int j = idx >> 6, d = idx & 63;
            int m = m0 + j;
            sB[j][d] = (m < Nc) ? hidden[((size_t)(b * Nc + m) * Tc + t) * Dc + d] : 0.f;
        }
        __syncthreads();
        #pragma unroll
        for (int j = 0; j < 16; j++) {
            float a0 = sA[r0][j], a1 = sA[r0 + 1][j], a2 = sA[r0 + 2][j], a3 = sA[r0 + 3][j];
            float4 bb = *(const float4*)&sB[j][c0];
            acc[0][0] += a0 * bb.x; acc[0][1] += a0 * bb.y; acc[0][2] += a0 * bb.z; acc[0][3] += a0 * bb.w;
            acc[1][0] += a1 * bb.x; acc[1][1] += a1 * bb.y; acc[1][2] += a1 * bb.z; acc[1][3] += a1 * bb.w;
            acc[2][0] += a2 * bb.x; acc[2][1] += a2 * bb.y; acc[2][2] += a2 * bb.z; acc[2][3] += a2 * bb.w;
            acc[3][0] += a3 * bb.x; acc[3][1] += a3 * bb.y; acc[3][2] += a3 * bb.z; acc[3][3] += a3 * bb.w;
        }
        __syncthreads();
    }
    #pragma unroll
    for (int rr = 0; rr < 4; rr++)
        *(float4*)&sS[r0 + rr][c0] = make_float4(acc[rr][0], acc[rr][1], acc[rr][2], acc[rr][3]);
    __syncthreads();

    float acc2[4][4] = {};
    #pragma unroll
    for (int d = 0; d < 64; d++) {
        float a0 = sS[r0][d], a1 = sS[r0 + 1][d], a2 = sS[r0 + 2][d], a3 = sS[r0 + 3][d];
        float4 w = *(const float4*)&sW[d][c0];
        acc2[0][0] += a0 * w.x; acc2[0][1] += a0 * w.y; acc2[0][2] += a0 * w.z; acc2[0][3] += a0 * w.w;
        acc2[1][0] += a1 * w.x; acc2[1][1] += a1 * w.y; acc2[1][2] += a1 * w.z; acc2[1][3] += a1 * w.w;
        acc2[2][0] += a2 * w.x; acc2[2][1] += a2 * w.y; acc2[2][2] += a2 * w.z; acc2[2][3] += a2 * w.w;
        acc2[3][0] += a3 * w.x; acc2[3][1] += a3 * w.y; acc2[3][2] += a3 * w.z; acc2[3][3] += a3 * w.w;
    }
    float4 gb = *(const float4*)&gcn_b[c0];
    #pragma unroll
    for (int rr = 0; rr < 4; rr++) {
        int n = n0 + r0 + rr;
        if (n < Nc) {
            float4 o;
            o.x = fmaxf(acc2[rr][0] + gb.x, 0.f);
            o.y = fmaxf(acc2[rr][1] + gb.y, 0.f);
            o.z = fmaxf(acc2[rr][2] + gb.z, 0.f);
            o.w = fmaxf(acc2[rr][3] + gb.w, 0.f);
            *(float4*)&g_gcn[((size_t)(b * Nc + n) * Tc + t) * Dc + c0] = o;
        }
    }
}

// ---------------- Kernel 3: Weff build (fp16 out), W in regs, 32 rows/block -----
__global__ __launch_bounds__(256) void k_weff(const float* __restrict__ WQ,
                                              const float* __restrict__ WK,
                                              const float* __restrict__ WV,
                                              const float* __restrict__ node_emb) {
    __shared__ float s_emb[32][16];
    int tid = threadIdx.x;
    int cx = blockIdx.x;   // 16 chunks of 1024 cols
    int by = blockIdx.y;   // 82 groups of 32 bn rows
    int X  = blockIdx.z;   // 0=Q,1=K,2=V
    const float* W = (X == 0) ? WQ : (X == 1) ? WK : WV;
    int c0 = cx * 1024 + tid * 4;

    float4 w[16];
    #pragma unroll
    for (int m = 0; m < 16; m++) w[m] = *(const float4*)&W[(size_t)m * 16384 + c0];

    for (int idx = tid; idx < 512; idx += 256) {
        int row = idx >> 4, m = idx & 15;
        int bn = by * 32 + row;
        if (bn < BNc) {
            int b = bn / Nc, n = bn - b * Nc;
            s_emb[row][m] = node_emb[n * Mc + m] * g_tfeat[b * Mc + m];
        }
    }
    __syncthreads();

    #pragma unroll 4
    for (int row = 0; row < 32; row++) {
        int bn = by * 32 + row;
        if (bn >= BNc) break;
        float4 acc = make_float4(0.f, 0.f, 0.f, 0.f);
        #pragma unroll
        for (int m = 0; m < 16; m++) {
            float e = s_emb[row][m];
            acc.x += e * w[m].x; acc.y += e * w[m].y;
            acc.z += e * w[m].z; acc.w += e * w[m].w;
        }
        __half2 h0 = __floats2half2_rn(acc.x, acc.y);
        __half2 h1 = __floats2half2_rn(acc.z, acc.w);
        __half2* dst = (__half2*)&g_weff[((size_t)X * BNc + bn) * 16384 + c0];
        dst[0] = h0; dst[1] = h1;
    }
}

// ---------------- Kernel 4: fused per-(b,n) attention path ----------------------
// smem layout (float units):
//   [0, 3168)      s_qkv           | overlay: s_sc (8*577=4616 spans [0,6240))
//   [3168, 6240)   s_w (fp16 double buf, 2*6144B)
//   [6240, 9408)   s_q             | overlay: s_val
//   [9408, 12576)  s_k
//   [12576, 15744) s_v             | overlay: s_value [12576,14112) + s_gcn [14112,15648)
#define ATTN_SMEM_FLOATS 15744
#define ATTN_SMEM_BYTES  (ATTN_SMEM_FLOATS * 4)

__global__ __launch_bounds__(256, 3) void k_attn(const float* __restrict__ hidden,
                                                 const float* __restrict__ tXin,
                                                 const float* __restrict__ out_w,
                                                 const float* __restrict__ out_b,
                                                 const float* __restrict__ gate_w,
                                                 const float* __restrict__ gate_b,
                                                 float* __restrict__ out) {
    extern __shared__ float sm[];
    float* s_qkv   = sm;               // 24*132
    float* s_sc    = sm;               // overlay 8*577
    float* s_q     = sm + 6240;
    float* s_k     = sm + 9408;
    float* s_v     = sm + 12576;
    float* s_val   = s_q;              // overlay after scores
    float* s_value = sm + 12576;       // overlay after AV
    float* s_gcn   = sm + 14112;       // overlay after AV

    int tid = threadIdx.x;
    int bn  = blockIdx.x;
    size_t base = (size_t)bn * (Tc * Dc);

    // ---- stage qkv ----
    for (int idx = tid; idx < 3072; idx += 256) {
        int t = idx >> 7, i = idx & 127;
        float vv = (i < 64) ? hidden[base + t * 64 + i] : tXin[base + t * 64 + (i - 64)];
        s_qkv[t * PAD + i] = vv;
    }

    const __half* wq = g_weff + (size_t)bn * 16384;
    const __half* wk = g_weff + ((size_t)BNc + bn) * 16384;
    const __half* wv = g_weff + ((size_t)2 * BNc + bn) * 16384;

    unsigned s_w_base = (unsigned)__cvta_generic_to_shared(sm + 3168);

    // stage = 8 i-rows: per X 8*128 halfs = 2048B; 3X = 6144B per buffer
    // prefetch stage 0 into buf 0: 384 x 16B transfers
    {
        #pragma unroll
        for (int rep = 0; rep < 2; rep++) {
            int j = tid + rep * 256;
            if (j < 384) {
                int X = j >> 7, jj = j & 127;
                const __half* src = ((X == 0) ? wq : (X == 1) ? wk : wv) + jj * 8;
                CP_ASYNC16(s_w_base + X * 2048 + jj * 16, src);
            }
        }
        CP_COMMIT();
    }

    int kg = tid & 63, tg = tid >> 6;   // 64 col-groups (2 cols) x 4 t-groups (6 rows)
    int tg6 = tg * 6;
    float2 acc[3][6] = {};

    int buf = 0;
    for (int it = 0; it < 16; it++) {
        if (it < 15) {
            #pragma unroll
            for (int rep = 0; rep < 2; rep++) {
                int j = tid + rep * 256;
                if (j < 384) {
                    int X = j >> 7, jj = j & 127;
                    const __half* src = ((X == 0) ? wq : (X == 1) ? wk : wv)
                                        + (it + 1) * 1024 + jj * 8;
                    CP_ASYNC16(s_w_base + (buf ^ 1) * 6144 + X * 2048 + jj * 16, src);
                }
            }
            CP_COMMIT();
            CP_WAIT1();
        } else {
            CP_WAIT0();
        }
        __syncthreads();
        const __half2* wb2 = (const __half2*)((const char*)sm + 3168 * 4 + buf * 6144);
        #pragma unroll
        for (int i = 0; i < 8; i++) {
            int ig = it * 8 + i;
            float a[6];
            #pragma unroll
            for (int r = 0; r < 6; r++) a[r] = s_qkv[(tg6 + r) * PAD + ig];
            #pragma unroll
            for (int X = 0; X < 3; X++) {
                // per-X slab = 8 rows * 128 halfs = 512 half2
                float2 wf = __half22float2(wb2[X * 512 + i * 64 + kg]);
                #pragma unroll
                for (int r = 0; r < 6; r++) {
                    acc[X][r].x += a[r] * wf.x;
                    acc[X][r].y += a[r] * wf.y;
                }
            }
        }
        __syncthreads();
        buf ^= 1;
    }

    // ---- store q,k,v with lrelu ----
    #pragma unroll
    for (int X = 0; X < 3; X++) {
        float* dst = (X == 0) ? s_q : (X == 1) ? s_k : s_v;
        #pragma unroll
        for (int r = 0; r < 6; r++) {
            float2 o;
            o.x = lrelu(acc[X][r].x);
            o.y = lrelu(acc[X][r].y);
            *(float2*)&dst[(tg6 + r) * PAD + kg * 2] = o;
        }
    }
    __syncthreads();

    // ---- scores (causal): overlay region [0,4616) over dead qkv/s_w ----
    for (int idx = tid; idx < 4608; idx += 256) {
        int h = idx / 576; int r = idx - h * 576; int t = r / 24; int s = r - t * 24;
        if (s <= t) {
            const float* qp = &s_q[t * PAD + h * 16];
            const float* kp = &s_k[s * PAD + h * 16];
            float d = 0.f;
            #pragma unroll
            for (int e = 0; e < 16; e++) d += qp[e] * kp[e];
            s_sc[h * 577 + t * 24 + s] = 0.25f * d;  // 1/sqrt(16)
        }
    }
    __syncthreads();

    // ---- softmax per (h,t) row ----
    if (tid < 192) {
        int h = tid / 24, t = tid % 24;
        float* row = &s_sc[h * 577 + t * 24];
        float mx = -1e30f;
        for (int s = 0; s <= t; s++) mx = fmaxf(mx, row[s]);
        float sum = 0.f;
        for (int s = 0; s <= t; s++) { float e = expf(row[s] - mx); row[s] = e; sum += e; }
        float inv = 1.f / sum;
        for (int s = 0; s < Tc; s++) row[s] = (s <= t) ? row[s] * inv : 0.f;
    }
    __syncthreads();

    // ---- val = attn @ v  (writes overlay over s_q) ----
    {
        int h = kg >> 3;
        float2 a2[6] = {};
        #pragma unroll
        for (int s = 0; s < Tc; s++) {
            float2 v2 = *(const float2*)&s_v[s * PAD + kg * 2];
            #pragma unroll
            for (int r = 0; r < 6; r++) {
                float a = s_sc[h * 577 + (tg6 + r) * 24 + s];
                a2[r].x += a * v2.x;
                a2[r].y += a * v2.y;
            }
        }
        __syncthreads();  // all s_q reads (scores) long done; safe ordering for overlay
        #pragma unroll
        for (int r = 0; r < 6; r++)
            *(float2*)&s_val[(tg6 + r) * PAD + kg * 2] = a2[r];
    }
    __syncthreads();

    // ---- load gcn under out-proj compute (s_v region now dead) ----
    for (int idx = tid; idx < 1536; idx += 256) s_gcn[idx] = g_gcn[base + idx];

    // ---- value = lrelu(val @ out_w + out_b) ----
    int e0 = (tid & 15) * 4;
    int tg2 = tid >> 4;               // 0..15
    int t0 = tg2, t1 = tg2 + 16;
    int t1c = (t1 < Tc) ? t1 : 0;
    {
        float a0[4] = {}, a1[4] = {};
        #pragma unroll 4
        for (int i = 0; i < 128; i++) {
            float4 w4 = *(const float4*)&out_w[i * 64 + e0];
            float x0 = s_val[t0 * PAD + i];
            float x1 = s_val[t1c * PAD + i];
            a0[0] += x0 * w4.x; a0[1] += x0 * w4.y; a0[2] += x0 * w4.z; a0[3] += x0 * w4.w;
            a1[0] += x1 * w4.x; a1[1] += x1 * w4.y; a1[2] += x1 * w4.z; a1[3] += x1 * w4.w;
        }
        float4 ob = *(const float4*)&out_b[e0];
        float4 v0;
        v0.x = lrelu(a0[0] + ob.x); v0.y = lrelu(a0[1] + ob.y);
        v0.z = lrelu(a0[2] + ob.z); v0.w = lrelu(a0[3] + ob.w);
        *(float4*)&s_value[t0 * 64 + e0] = v0;
        if (t1 < Tc) {
            float4 v1;
            v1.x = lrelu(a1[0] + ob.x); v1.y = lrelu(a1[1] + ob.y);
            v1.z = lrelu(a1[2] + ob.z); v1.w = lrelu(a1[3] + ob.w);
            *(float4*)&s_value[t1 * 64 + e0] = v1;
        }
    }
    __syncthreads();

    // ---- gate + blend + residual ----
    {
        float g0[4] = {}, g1[4] = {};
        #pragma unroll 4
        for (int i = 0; i < 64; i++) {
            float4 w4 = *(const float4*)&gate_w[i * 64 + e0];
            float x0 = s_gcn[t0 * 64 + i];
            float x1 = s_gcn[t1c * 64 + i];
            g0[0] += x0 * w4.x; g0[1] += x0 * w4.y; g0[2] += x0 * w4.z; g0[3] += x0 * w4.w;
            g1[0] += x1 * w4.x; g1[1] += x1 * w4.y; g1[2] += x1 * w4.z; g1[3] += x1 * w4.w;
        }
        #pragma unroll 4
        for (int i = 0; i < 64; i++) {
            float4 w4 = *(const float4*)&gate_w[(64 + i) * 64 + e0];
            float x0 = s_value[t0 * 64 + i];
            float x1 = s_value[t1c * 64 + i];
            g0[0] += x0 * w4.x; g0[1] += x0 * w4.y; g0[2] += x0 * w4.z; g0[3] += x0 * w4.w;
            g1[0] += x1 * w4.x; g1[1] += x1 * w4.y; g1[2] += x1 * w4.z; g1[3] += x1 * w4.w;
        }
        float4 gb = *(const float4*)&gate_b[e0];
        {
            float4 hd = *(const float4*)&hidden[base + t0 * 64 + e0];
            float zx = 1.f / (1.f + expf(-(g0[0] + gb.x)));
            float zy = 1.f / (1.f + expf(-(g0[1] + gb.y)));
            float zz = 1.f / (1.f + expf(-(g0[2] + gb.z)));
            float zw = 1.f / (1.f + expf(-(g0[3] + gb.w)));
            const float* gc = &s_gcn[t0 * 64 + e0];
            const float* vv = &s_value[t0 * 64 + e0];
            float4 o;
            o.x = zx * gc[0] + (1.f - zx) * vv[0] + hd.x;
            o.y = zy * gc[1] + (1.f - zy) * vv[1] + hd.y;
            o.z = zz * gc[2] + (1.f - zz) * vv[2] + hd.z;
            o.w = zw * gc[3] + (1.f - zw) * vv[3] + hd.w;
            *(float4*)&out[base + t0 * 64 + e0] = o;
        }
        if (t1 < Tc) {
            float4 hd = *(const float4*)&hidden[base + t1 * 64 + e0];
            float zx = 1.f / (1.f + expf(-(g1[0] + gb.x)));
            float zy = 1.f / (1.f + expf(-(g1[1] + gb.y)));
            float zz = 1.f / (1.f + expf(-(g1[2] + gb.z)));
            float zw = 1.f / (1.f + expf(-(g1[3] + gb.w)));
            const float* gc = &s_gcn[t1 * 64 + e0];
            const float* vv = &s_value[t1 * 64 + e0];
            float4 o;
            o.x = zx * gc[0] + (1.f - zx) * vv[0] + hd.x;
            o.y = zy * gc[1] + (1.f - zy) * vv[1] + hd.y;
            o.z = zz * gc[2] + (1.f - zz) * vv[2] + hd.z;
            o.w = zw * gc[3] + (1.f - zw) * vv[3] + hd.w;
            *(float4*)&out[base + t1 * 64 + e0] = o;
        }
    }
}

// ---------------- launch ----------------
extern "C" void kernel_launch(void* const* d_in, const int* in_sizes, int n_in,
                              void* d_out, int out_size) {
    const float* hidden   = (const float*)d_in[0];
    const float* tXin     = (const float*)d_in[1];
    const float* matrix   = (const float*)d_in[2];
    const float* gcn_w    = (const float*)d_in[3];
    const float* gcn_b    = (const float*)d_in[4];
    const float* node_emb = (const float*)d_in[5];
    const float* tproj_w  = (const float*)d_in[6];
    const float* tproj_b  = (const float*)d_in[7];
    const float* WK       = (const float*)d_in[8];
    const float* WQ       = (const float*)d_in[9];
    const float* WV       = (const float*)d_in[10];
    const float* out_w    = (const float*)d_in[11];
    const float* out_b    = (const float*)d_in[12];
    const float* gate_w   = (const float*)d_in[13];
    const float* gate_b   = (const float*)d_in[14];
    float* out = (float*)d_out;

    cudaFuncSetAttribute(k_attn, cudaFuncAttributeMaxDynamicSharedMemorySize, ATTN_SMEM_BYTES);

    k_tfeat<<<Bc, 64>>>(tXin, tproj_w, tproj_b);
    k_gcn<<<dim3(6, Tc, Bc), 256>>>(matrix, hidden, gcn_w, gcn_b);
    k_weff<<<dim3(16, 82, 3), 256>>>(WQ, WK, WV, node_emb);
    k_attn<<<BNc, 256, ATTN_SMEM_BYTES>>>(hidden, tXin, out_w, out_b, gate_w, gate_b, out);
}

// round 6
// speedup vs baseline: 1.9046x; 1.1773x over previous
#include <cuda_runtime.h>
#include <cuda_fp16.h>
#include <math.h>

#define Bc   8
#define Nc   325
#define Tc   24
#define Dc   64
#define Hc   8
#define Mc   16
#define E2c  128
#define BNc  2600   // Bc*Nc
#define PAD  132    // padded row stride for T x E2 fp32 smem tiles

// ---------------- device scratch ----------------
__device__ float g_tfeat[Bc * Mc];                            // (B,16)
__device__ float g_gcn[(size_t)Bc * Nc * Tc * Dc];            // (B,N,T,D) ~16MB
__device__ __align__(16) __half g_weff[(size_t)3 * BNc * E2c * E2c]; // fp16 ~256MB

__device__ __forceinline__ float lrelu(float x) { return x > 0.f ? x : 0.1f * x; }

#define CP_ASYNC16(sdst, gsrc) \
    asm volatile("cp.async.cg.shared.global [%0], [%1], 16;" :: "r"(sdst), "l"(gsrc) : "memory")
#define CP_COMMIT() asm volatile("cp.async.commit_group;" ::: "memory")
#define CP_WAIT1()  asm volatile("cp.async.wait_group 1;" ::: "memory")
#define CP_WAIT0()  asm volatile("cp.async.wait_group 0;" ::: "memory")

__device__ __forceinline__ void ldsm_x4(unsigned* r, unsigned addr) {
    asm volatile("ldmatrix.sync.aligned.m8n8.x4.shared.b16 {%0,%1,%2,%3}, [%4];"
                 : "=r"(r[0]), "=r"(r[1]), "=r"(r[2]), "=r"(r[3]) : "r"(addr));
}
__device__ __forceinline__ void ldsm_x4_t(unsigned* r, unsigned addr) {
    asm volatile("ldmatrix.sync.aligned.m8n8.x4.trans.shared.b16 {%0,%1,%2,%3}, [%4];"
                 : "=r"(r[0]), "=r"(r[1]), "=r"(r[2]), "=r"(r[3]) : "r"(addr));
}
__device__ __forceinline__ void mma16816(float* c, const unsigned* a, unsigned b0, unsigned b1) {
    asm volatile("mma.sync.aligned.m16n8k16.row.col.f32.f16.f16.f32 "
                 "{%0,%1,%2,%3}, {%4,%5,%6,%7}, {%8,%9}, {%0,%1,%2,%3};"
                 : "+f"(c[0]), "+f"(c[1]), "+f"(c[2]), "+f"(c[3])
                 : "r"(a[0]), "r"(a[1]), "r"(a[2]), "r"(a[3]), "r"(b0), "r"(b1));
}

// ---------------- Kernel 1: tfeat ----------------
__global__ void k_tfeat(const float* __restrict__ tXin,
                        const float* __restrict__ tpw,
                        const float* __restrict__ tpb) {
    __shared__ float s_mean[Dc];
    int b = blockIdx.x;
    int d = threadIdx.x;  // 64 threads
    const float* p = tXin + (size_t)b * Nc * Tc * Dc;  // n = 0 slice
    float s = 0.f;
    #pragma unroll
    for (int t = 0; t < Tc; t++) s += p[t * Dc + d];
    s_mean[d] = s * (1.0f / Tc);
    __syncthreads();
    if (d < Mc) {
        float acc = tpb[d];
        #pragma unroll
        for (int i = 0; i < Dc; i++) acc += s_mean[i] * tpw[i * Mc + d];
        g_tfeat[b * Mc + d] = tanhf(acc);
    }
}

// ---------------- Kernel 2: support GEMM + GCN (fused) --------------------------
__global__ __launch_bounds__(256) void k_gcn(const float* __restrict__ matrix,
                                             const float* __restrict__ hidden,
                                             const float* __restrict__ gcn_w,
                                             const float* __restrict__ gcn_b) {
    __shared__ float sA[64][17];
    __shared__ float sB[16][68];
    __shared__ float sS[64][68];
    __shared__ float sW[64][68];
    int tid = threadIdx.x;
    int nt = blockIdx.x, t = blockIdx.y, b = blockIdx.z;
    int n0 = nt * 64;

    for (int idx = tid; idx < 4096; idx += 256) sW[idx >> 6][idx & 63] = gcn_w[idx];

    int ty = tid >> 4, tx = tid & 15;
    int r0 = ty * 4, c0 = tx * 4;
    float acc[4][4] = {};
    const float* Mrow = matrix + ((size_t)(b * Tc + t) * Nc) * Nc;

    for (int kb = 0; kb < 21; kb++) {
        int m0 = kb * 16;
        for (int idx = tid; idx < 1024; idx += 256) {
            int i = idx >> 4, j = idx & 15;
            int n = n0 + i, m = m0 + j;
            sA[i][j] = (n < Nc && m < Nc) ? Mrow[(size_t)n * Nc + m] : 0.f;
        }
        for (int idx = tid; idx < 1024; idx += 256) {
            int j = idx >> 6, d = idx & 63;
            int m = m0 + j;
            sB[j][d] = (m < Nc) ? hidden[((size_t)(b * Nc + m) * Tc + t) * Dc + d] : 0.f;
        }
        __syncthreads();
        #pragma unroll
        for (int j = 0; j < 16; j++) {
            float a0 = sA[r0][j], a1 = sA[r0 + 1][j], a2 = sA[r0 + 2][j], a3 = sA[r0 + 3][j];
            float4 bb = *(const float4*)&sB[j][c0];
            acc[0][0] += a0 * bb.x; acc[0][1] += a0 * bb.y; acc[0][2] += a0 * bb.z; acc[0][3] += a0 * bb.w;
            acc[1][0] += a1 * bb.x; acc[1][1] += a1 * bb.y; acc[1][2] += a1 * bb.z; acc[1][3] += a1 * bb.w;
            acc[2][0] += a2 * bb.x; acc[2][1] += a2 * bb.y; acc[2][2] += a2 * bb.z; acc[2][3] += a2 * bb.w;
            acc[3][0] += a3 * bb.x; acc[3][1] += a3 * bb.y; acc[3][2] += a3 * bb.z; acc[3][3] += a3 * bb.w;
        }
        __syncthreads();
    }
    #pragma unroll
    for (int rr = 0; rr < 4; rr++)
        *(float4*)&sS[r0 + rr][c0] = make_float4(acc[rr][0], acc[rr][1], acc[rr][2], acc[rr][3]);
    __syncthreads();

    float acc2[4][4] = {};
    #pragma unroll
    for (int d = 0; d < 64; d++) {
        float a0 = sS[r0][d], a1 = sS[r0 + 1][d], a2 = sS[r0 + 2][d], a3 = sS[r0 + 3][d];
        float4 w = *(const float4*)&sW[d][c0];
        acc2[0][0] += a0 * w.x; acc2[0][1] += a0 * w.y; acc2[0][2] += a0 * w.z; acc2[0][3] += a0 * w.w;
        acc2[1][0] += a1 * w.x; acc2[1][1] += a1 * w.y; acc2[1][2] += a1 * w.z; acc2[1][3] += a1 * w.w;
        acc2[2][0] += a2 * w.x; acc2[2][1] += a2 * w.y; acc2[2][2] += a2 * w.z; acc2[2][3] += a2 * w.w;
        acc2[3][0] += a3 * w.x; acc2[3][1] += a3 * w.y; acc2[3][2] += a3 * w.z; acc2[3][3] += a3 * w.w;
    }
    float4 gb = *(const float4*)&gcn_b[c0];
    #pragma unroll
    for (int rr = 0; rr < 4; rr++) {
        int n = n0 + r0 + rr;
        if (n < Nc) {
            float4 o;
            o.x = fmaxf(acc2[rr][0] + gb.x, 0.f);
            o.y = fmaxf(acc2[rr][1] + gb.y, 0.f);
            o.z = fmaxf(acc2[rr][2] + gb.z, 0.f);
            o.w = fmaxf(acc2[rr][3] + gb.w, 0.f);
            *(float4*)&g_gcn[((size_t)(b * Nc + n) * Tc + t) * Dc + c0] = o;
        }
    }
}

// ---------------- Kernel 3: Weff build (fp16 out), W in regs, 32 rows/block -----
__global__ __launch_bounds__(256) void k_weff(const float* __restrict__ WQ,
                                              const float* __restrict__ WK,
                                              const float* __restrict__ WV,
                                              const float* __restrict__ node_emb) {
    __shared__ float s_emb[32][16];
    int tid = threadIdx.x;
    int cx = blockIdx.x;   // 16 chunks of 1024 cols
    int by = blockIdx.y;   // 82 groups of 32 bn rows
    int X  = blockIdx.z;   // 0=Q,1=K,2=V
    const float* W = (X == 0) ? WQ : (X == 1) ? WK : WV;
    int c0 = cx * 1024 + tid * 4;

    float4 w[16];
    #pragma unroll
    for (int m = 0; m < 16; m++) w[m] = *(const float4*)&W[(size_t)m * 16384 + c0];

    for (int idx = tid; idx < 512; idx += 256) {
        int row = idx >> 4, m = idx & 15;
        int bn = by * 32 + row;
        if (bn < BNc) {
            int b = bn / Nc, n = bn - b * Nc;
            s_emb[row][m] = node_emb[n * Mc + m] * g_tfeat[b * Mc + m];
        }
    }
    __syncthreads();

    #pragma unroll 4
    for (int row = 0; row < 32; row++) {
        int bn = by * 32 + row;
        if (bn >= BNc) break;
        float4 acc = make_float4(0.f, 0.f, 0.f, 0.f);
        #pragma unroll
        for (int m = 0; m < 16; m++) {
            float e = s_emb[row][m];
            acc.x += e * w[m].x; acc.y += e * w[m].y;
            acc.z += e * w[m].z; acc.w += e * w[m].w;
        }
        __half2 h0 = __floats2half2_rn(acc.x, acc.y);
        __half2 h1 = __floats2half2_rn(acc.z, acc.w);
        __half2* dst = (__half2*)&g_weff[((size_t)X * BNc + bn) * 16384 + c0];
        dst[0] = h0; dst[1] = h1;
    }
}

// ---------------- Kernel 4: fused per-(b,n) attention path ----------------------
// smem (float units), total 14120 floats = 56480B:
//   phase1: s_act fp16 32x136  [0,2176) | s_w fp16 2buf x 16x136 rows [2176,4352)
//   phase2: s_sc overlay [0,4616)
//   s_q [4616,7784) | s_val overlay
//   s_k [7784,10952)
//   s_v [10952,14120) | s_value [10952,12488) + s_gcn [12488,14024) overlay
#define ATTN_SMEM_FLOATS 14120
#define ATTN_SMEM_BYTES  (ATTN_SMEM_FLOATS * 4)

__global__ __launch_bounds__(256, 4) void k_attn(const float* __restrict__ hidden,
                                                 const float* __restrict__ tXin,
                                                 const float* __restrict__ out_w,
                                                 const float* __restrict__ out_b,
                                                 const float* __restrict__ gate_w,
                                                 const float* __restrict__ gate_b,
                                                 float* __restrict__ out) {
    extern __shared__ float sm[];
    __half* s_act  = (__half*)sm;      // 32x136 halfs
    float* s_sc    = sm;               // overlay 8*577
    float* s_q     = sm + 4616;
    float* s_k     = sm + 7784;
    float* s_v     = sm + 10952;
    float* s_val   = s_q;              // overlay after scores
    float* s_value = sm + 10952;       // overlay after AV
    float* s_gcn   = sm + 12488;       // overlay after AV

    int tid  = threadIdx.x;
    int lane = tid & 31;
    int warp = tid >> 5;
    int bn   = blockIdx.x;
    size_t base = (size_t)bn * (Tc * Dc);

    // ---- stage activations as fp16 (rows 24-31 zero) ----
    for (int idx = tid; idx < 4096; idx += 256) {
        int t = idx >> 7, i = idx & 127;
        float vv = 0.f;
        if (t < Tc) vv = (i < 64) ? hidden[base + t * 64 + i] : tXin[base + t * 64 + (i - 64)];
        s_act[t * 136 + i] = __float2half(vv);
    }

    const __half* wq = g_weff + (size_t)bn * 16384;
    const __half* wk = g_weff + ((size_t)BNc + bn) * 16384;
    const __half* wv = g_weff + ((size_t)2 * BNc + bn) * 16384;

    unsigned act_base = (unsigned)__cvta_generic_to_shared(s_act);
    unsigned w_base   = act_base + 8704;   // s_w starts at float 2176

    // weight stage: 16 i-rows x 128 halfs, padded rows 272B; 256 transfers = 1/thread
    int srow = tid >> 4, sseg = tid & 15;
    unsigned sdst_off = srow * 272 + sseg * 16;
    int ssrc_off = srow * 128 + sseg * 8;

    // prefetch stage 0 (X=0, i0=0) into buf 0
    CP_ASYNC16(w_base + sdst_off, wq + ssrc_off);
    CP_COMMIT();

    // ldmatrix per-lane offsets
    int arow = (lane & 7) + (lane & 8);          // 0..15
    int acol = (lane & 16) ? 8 : 0;
    unsigned a_off0 = (arow * 136 + acol) * 2;               // mt=0
    unsigned a_off1 = ((16 + arow) * 136 + acol) * 2;        // mt=1
    int wn = warp * 16;
    unsigned b_off = (arow * 136 + wn + acol) * 2;           // within stage buf

    int trow = lane >> 2, tcol = (lane & 3) * 2;

    int buf = 0;
    for (int X = 0; X < 3; X++) {
        float acc[2][2][4] = {};   // [nt][mt][4]
        for (int kk = 0; kk < 8; kk++) {
            int s = X * 8 + kk;
            if (s < 23) {
                int s1 = s + 1;
                int X1 = s1 >> 3, i0 = (s1 & 7) * 16;
                const __half* w = (X1 == 0) ? wq : (X1 == 1) ? wk : wv;
                CP_ASYNC16(w_base + (buf ^ 1) * 4352 + sdst_off, w + i0 * 128 + ssrc_off);
                CP_COMMIT();
                CP_WAIT1();
            } else {
                CP_WAIT0();
            }
            __syncthreads();

            unsigned a0f[4], a1f[4], bf[4];
            ldsm_x4(a0f, act_base + a_off0 + kk * 32);
            ldsm_x4(a1f, act_base + a_off1 + kk * 32);
            ldsm_x4_t(bf, w_base + buf * 4352 + b_off);
            mma16816(acc[0][0], a0f, bf[0], bf[1]);
            mma16816(acc[0][1], a1f, bf[0], bf[1]);
            mma16816(acc[1][0], a0f, bf[2], bf[3]);
            mma16816(acc[1][1], a1f, bf[2], bf[3]);

            __syncthreads();
            buf ^= 1;
        }
        // store lrelu(result) to s_q/k/v
        float* dst = (X == 0) ? s_q : (X == 1) ? s_k : s_v;
        #pragma unroll
        for (int nt = 0; nt < 2; nt++) {
            int colb = wn + nt * 8 + tcol;
            {   // mt = 0: rows trow, trow+8
                float* c = acc[nt][0];
                *(float2*)&dst[trow * PAD + colb] = make_float2(lrelu(c[0]), lrelu(c[1]));
                *(float2*)&dst[(trow + 8) * PAD + colb] = make_float2(lrelu(c[2]), lrelu(c[3]));
            }
            {   // mt = 1: rows 16+trow only (24+trow is padding)
                float* c = acc[nt][1];
                *(float2*)&dst[(16 + trow) * PAD + colb] = make_float2(lrelu(c[0]), lrelu(c[1]));
            }
        }
    }
    __syncthreads();

    // ---- scores (causal): overlay region [0,4616) ----
    for (int idx = tid; idx < 4608; idx += 256) {
        int h = idx / 576; int r = idx - h * 576; int t = r / 24; int s = r - t * 24;
        if (s <= t) {
            const float* qp = &s_q[t * PAD + h * 16];
            const float* kp = &s_k[s * PAD + h * 16];
            float d = 0.f;
            #pragma unroll
            for (int e = 0; e < 16; e++) d += qp[e] * kp[e];
            s_sc[h * 577 + t * 24 + s] = 0.25f * d;  // 1/sqrt(16)
        }
    }
    __syncthreads();

    // ---- softmax per (h,t) row ----
    if (tid < 192) {
        int h = tid / 24, t = tid % 24;
        float* row = &s_sc[h * 577 + t * 24];
        float mx = -1e30f;
        for (int s = 0; s <= t; s++) mx = fmaxf(mx, row[s]);
        float sum = 0.f;
        for (int s = 0; s <= t; s++) { float e = expf(row[s] - mx); row[s] = e; sum += e; }
        float inv = 1.f / sum;
        for (int s = 0; s < Tc; s++) row[s] = (s <= t) ? row[s] * inv : 0.f;
    }
    __syncthreads();

    // ---- val = attn @ v  (writes overlay over s_q) ----
    {
        int kg = tid & 63, tg = tid >> 6;
        int tg6 = tg * 6;
        int h = kg >> 3;
        float2 a2[6] = {};
        #pragma unroll
        for (int s = 0; s < Tc; s++) {
            float2 v2 = *(const float2*)&s_v[s * PAD + kg * 2];
            #pragma unroll
            for (int r = 0; r < 6; r++) {
                float a = s_sc[h * 577 + (tg6 + r) * 24 + s];
                a2[r].x += a * v2.x;
                a2[r].y += a * v2.y;
            }
        }
        __syncthreads();
        #pragma unroll
        for (int r = 0; r < 6; r++)
            *(float2*)&s_val[(tg6 + r) * PAD + kg * 2] = a2[r];
    }
    __syncthreads();

    // ---- load gcn under out-proj compute (s_v region now dead) ----
    for (int idx = tid; idx < 1536; idx += 256) s_gcn[idx] = g_gcn[base + idx];

    // ---- value = lrelu(val @ out_w + out_b) ----
    int e0 = (tid & 15) * 4;
    int tg2 = tid >> 4;               // 0..15
    int t0 = tg2, t1 = tg2 + 16;
    int t1c = (t1 < Tc) ? t1 : 0;
    {
        float a0[4] = {}, a1[4] = {};
        #pragma unroll 2
        for (int i = 0; i < 128; i += 4) {
            float4 x0 = *(const float4*)&s_val[t0 * PAD + i];
            float4 x1 = *(const float4*)&s_val[t1c * PAD + i];
            #pragma unroll
            for (int u = 0; u < 4; u++) {
                float4 w4 = *(const float4*)&out_w[(i + u) * 64 + e0];
                float xu0 = (&x0.x)[u], xu1 = (&x1.x)[u];
                a0[0] += xu0 * w4.x; a0[1] += xu0 * w4.y; a0[2] += xu0 * w4.z; a0[3] += xu0 * w4.w;
                a1[0] += xu1 * w4.x; a1[1] += xu1 * w4.y; a1[2] += xu1 * w4.z; a1[3] += xu1 * w4.w;
            }
        }
        float4 ob = *(const float4*)&out_b[e0];
        float4 v0;
        v0.x = lrelu(a0[0] + ob.x); v0.y = lrelu(a0[1] + ob.y);
        v0.z = lrelu(a0[2] + ob.z); v0.w = lrelu(a0[3] + ob.w);
        *(float4*)&s_value[t0 * 64 + e0] = v0;
        if (t1 < Tc) {
            float4 v1;
            v1.x = lrelu(a1[0] + ob.x); v1.y = lrelu(a1[1] + ob.y);
            v1.z = lrelu(a1[2] + ob.z); v1.w = lrelu(a1[3] + ob.w);
            *(float4*)&s_value[t1 * 64 + e0] = v1;
        }
    }
    __syncthreads();

    // ---- gate + blend + residual ----
    {
        float g0[4] = {}, g1[4] = {};
        #pragma unroll 2
        for (int i = 0; i < 64; i += 4) {
            float4 x0 = *(const float4*)&s_gcn[t0 * 64 + i];
            float4 x1 = *(const float4*)&s_gcn[t1c * 64 + i];
            #pragma unroll
            for (int u = 0; u < 4; u++) {
                float4 w4 = *(const float4*)&gate_w[(i + u) * 64 + e0];
                float xu0 = (&x0.x)[u], xu1 = (&x1.x)[u];
                g0[0] += xu0 * w4.x; g0[1] += xu0 * w4.y; g0[2] += xu0 * w4.z; g0[3] += xu0 * w4.w;
                g1[0] += xu1 * w4.x; g1[1] += xu1 * w4.y; g1[2] += xu1 * w4.z; g1[3] += xu1 * w4.w;
            }
        }
        #pragma unroll 2
        for (int i = 0; i < 64; i += 4) {
            float4 x0 = *(const float4*)&s_value[t0 * 64 + i];
            float4 x1 = *(const float4*)&s_value[t1c * 64 + i];
            #pragma unroll
            for (int u = 0; u < 4; u++) {
                float4 w4 = *(const float4*)&gate_w[(64 + i + u) * 64 + e0];
                float xu0 = (&x0.x)[u], xu1 = (&x1.x)[u];
                g0[0] += xu0 * w4.x; g0[1] += xu0 * w4.y; g0[2] += xu0 * w4.z; g0[3] += xu0 * w4.w;
                g1[0] += xu1 * w4.x; g1[1] += xu1 * w4.y; g1[2] += xu1 * w4.z; g1[3] += xu1 * w4.w;
            }
        }
        float4 gb = *(const float4*)&gate_b[e0];
        {
            float4 hd = *(const float4*)&hidden[base + t0 * 64 + e0];
            float zx = 1.f / (1.f + expf(-(g0[0] + gb.x)));
            float zy = 1.f / (1.f + expf(-(g0[1] + gb.y)));
            float zz = 1.f / (1.f + expf(-(g0[2] + gb.z)));
            float zw = 1.f / (1.f + expf(-(g0[3] + gb.w)));
            const float* gc = &s_gcn[t0 * 64 + e0];
            const float* vv = &s_value[t0 * 64 + e0];
            float4 o;
            o.x = zx * gc[0] + (1.f - zx) * vv[0] + hd.x;
            o.y = zy * gc[1] + (1.f - zy) * vv[1] + hd.y;
            o.z = zz * gc[2] + (1.f - zz) * vv[2] + hd.z;
            o.w = zw * gc[3] + (1.f - zw) * vv[3] + hd.w;
            *(float4*)&out[base + t0 * 64 + e0] = o;
        }
        if (t1 < Tc) {
            float4 hd = *(const float4*)&hidden[base + t1 * 64 + e0];
            float zx = 1.f / (1.f + expf(-(g1[0] + gb.x)));
            float zy = 1.f / (1.f + expf(-(g1[1] + gb.y)));
            float zz = 1.f / (1.f + expf(-(g1[2] + gb.z)));
            float zw = 1.f / (1.f + expf(-(g1[3] + gb.w)));
            const float* gc = &s_gcn[t1 * 64 + e0];
            const float* vv = &s_value[t1 * 64 + e0];
            float4 o;
            o.x = zx * gc[0] + (1.f - zx) * vv[0] + hd.x;
            o.y = zy * gc[1] + (1.f - zy) * vv[1] + hd.y;
            o.z = zz * gc[2] + (1.f - zz) * vv[2] + hd.z;
            o.w = zw * gc[3] + (1.f - zw) * vv[3] + hd.w;
            *(float4*)&out[base + t1 * 64 + e0] = o;
        }
    }
}

// ---------------- launch ----------------
extern "C" void kernel_launch(void* const* d_in, const int* in_sizes, int n_in,
                              void* d_out, int out_size) {
    const float* hidden   = (const float*)d_in[0];
    const float* tXin     = (const float*)d_in[1];
    const float* matrix   = (const float*)d_in[2];
    const float* gcn_w    = (const float*)d_in[3];
    const float* gcn_b    = (const float*)d_in[4];
    const float* node_emb = (const float*)d_in[5];
    const float* tproj_w  = (const float*)d_in[6];
    const float* tproj_b  = (const float*)d_in[7];
    const float* WK       = (const float*)d_in[8];
    const float* WQ       = (const float*)d_in[9];
    const float* WV       = (const float*)d_in[10];
    const float* out_w    = (const float*)d_in[11];
    const float* out_b    = (const float*)d_in[12];
    const float* gate_w   = (const float*)d_in[13];
    const float* gate_b   = (const float*)d_in[14];
    float* out = (float*)d_out;

    cudaFuncSetAttribute(k_attn, cudaFuncAttributeMaxDynamicSharedMemorySize, ATTN_SMEM_BYTES);

    k_tfeat<<<Bc, 64>>>(tXin, tproj_w, tproj_b);
    k_gcn<<<dim3(6, Tc, Bc), 256>>>(matrix, hidden, gcn_w, gcn_b);
    k_weff<<<dim3(16, 82, 3), 256>>>(WQ, WK, WV, node_emb);
    k_attn<<<BNc, 256, ATTN_SMEM_BYTES>>>(hidden, tXin, out_w, out_b, gate_w, gate_b, out);
}